// round 15
// baseline (speedup 1.0000x reference)
#include <cuda_runtime.h>
#include <cuda_fp16.h>
#include <math.h>

#define Hh 2048
#define Tt 4096
#define Dd 66
#define G4H (4*Hh)
#define NBLK 148
#define NTHR 512
#define NWARP (NTHR/32)
#define NJMAX 14
#define WELEM ((size_t)G4H*(size_t)Hh)
#define WSTRIDE ((size_t)Hh*(size_t)Hh)
// pinned: 3*nj rows W_hh1 (i,f,g) + 8 rows W_hh2 (units 0,1 all gates)
#define SWBYTES ((3*NJMAX + 8)*Hh*sizeof(__half))   // 204800 B
#define PACKED_ONE 0x3F8000003F800000ull

// ---------------- persistent device state (static; no runtime allocs) -------
__device__ __half g_h1h[2][Hh];                    // h1 double buffer, fp16
__device__ __half g_h2h[2][Hh];                    // h2 double buffer, fp16
__device__ float  g_h2hist[Tt][Hh];                // 33.5 MB (fp32, for proj)
__device__ __half g_pre1[(size_t)Tt * G4H];        // 67 MB fp16 (streamed, .cs)
__device__ __half g_whh1[WELEM];                   // 33.5 MB fp16
__device__ __half g_wih2[WELEM];
__device__ __half g_whh2[WELEM];

// flag barrier state (monotonic across graph replays) — central-release
__device__ volatile unsigned g_arrive[NBLK];
__device__ volatile unsigned g_release;

__device__ __forceinline__ float sigf(float x) { return 1.0f / (1.0f + expf(-x)); }

// ---------------- split central-release grid barrier --------------------------
__device__ __forceinline__ void gbar_arrive(unsigned target) {
    __syncthreads();
    if (blockIdx.x != 0 && threadIdx.x == 0) {
        __threadfence();
        g_arrive[blockIdx.x] = target;
    }
}
__device__ __forceinline__ void gbar_wait(unsigned target) {
    if (blockIdx.x == 0) {
        if (threadIdx.x > 0 && threadIdx.x < NBLK) {
            while ((int)(g_arrive[threadIdx.x] - target) < 0) { }
        }
        __syncthreads();
        if (threadIdx.x == 0) { __threadfence(); g_release = target; }
    } else {
        if (threadIdx.x == 0) {
            while ((int)(g_release - target) < 0) { }
            __threadfence();
        }
    }
    __syncthreads();
}

// ---------------- helpers ----------------------------------------------------
__device__ __forceinline__ float wreduce(float s) {
#pragma unroll
    for (int o = 16; o; o >>= 1) s += __shfl_down_sync(0xffffffffu, s, o);
    return s;
}

__device__ __forceinline__ unsigned long long cvt_h2_f2(unsigned h2) {
    unsigned long long r;
    asm("{\n\t"
        ".reg .f16 h0, h1;\n\t"
        ".reg .f32 f0, f1;\n\t"
        "mov.b32 {h0, h1}, %1;\n\t"
        "cvt.f32.f16 f0, h0;\n\t"
        "cvt.f32.f16 f1, h1;\n\t"
        "mov.b64 %0, {f0, f1};\n\t"
        "}" : "=l"(r) : "r"(h2));
    return r;
}

__device__ __forceinline__ void fma2(unsigned long long& acc,
                                     unsigned long long a,
                                     unsigned long long b) {
    asm("fma.rn.f32x2 %0, %1, %2, %3;" : "=l"(acc) : "l"(a), "l"(b), "l"(acc));
}

__device__ __forceinline__ float accsum(unsigned long long a) {
    float lo, hi;
    asm("mov.b64 {%0, %1}, %2;" : "=f"(lo), "=f"(hi) : "l"(a));
    return lo + hi;
}

// fp16 chunk-8 inner product (R13-proven): 1 HMUL2 + 3 HFMA2, one fp32x2 fold.
__device__ __forceinline__ void duh(uint4 w, uint4 h, unsigned long long& accf) {
    __half2 a =         __hmul2(*(__half2*)&w.x, *(__half2*)&h.x);
    a = __hfma2(*(__half2*)&w.y, *(__half2*)&h.y, a);
    a = __hfma2(*(__half2*)&w.z, *(__half2*)&h.z, a);
    a = __hfma2(*(__half2*)&w.w, *(__half2*)&h.w, a);
    fma2(accf, cvt_h2_f2(*(unsigned*)&a), PACKED_ONE);
}

// 4 gate rows streaming; h fp16 in smem (uint4-indexed)
__device__ __forceinline__ float4 dot4g(const __half* __restrict__ w0,
                                        const uint4* __restrict__ hv, int lane) {
    const uint4* p0 = (const uint4*)w0;
    const uint4* p1 = (const uint4*)(w0 + WSTRIDE);
    const uint4* p2 = (const uint4*)(w0 + 2 * WSTRIDE);
    const uint4* p3 = (const uint4*)(w0 + 3 * WSTRIDE);
    unsigned long long a0 = 0ull, a1 = 0ull, a2 = 0ull, a3 = 0ull;
#pragma unroll 2
    for (int k = 0; k < 8; k++) {
        int idx = k * 32 + lane;
        uint4 h = hv[idx];
        duh(p0[idx], h, a0);
        duh(p1[idx], h, a1);
        duh(p2[idx], h, a2);
        duh(p3[idx], h, a3);
    }
    return make_float4(wreduce(accsum(a0)), wreduce(accsum(a1)),
                       wreduce(accsum(a2)), wreduce(accsum(a3)));
}

// streaming with k=0 prefetched across the barrier window
__device__ __forceinline__ float4 dot4g_pf(const __half* __restrict__ w0,
                                           const uint4* __restrict__ hv, int lane,
                                           uint4 f0, uint4 f1, uint4 f2, uint4 f3) {
    const uint4* p0 = (const uint4*)w0;
    const uint4* p1 = (const uint4*)(w0 + WSTRIDE);
    const uint4* p2 = (const uint4*)(w0 + 2 * WSTRIDE);
    const uint4* p3 = (const uint4*)(w0 + 3 * WSTRIDE);
    unsigned long long a0 = 0ull, a1 = 0ull, a2 = 0ull, a3 = 0ull;
    {
        uint4 h = hv[lane];
        duh(f0, h, a0);
        duh(f1, h, a1);
        duh(f2, h, a2);
        duh(f3, h, a3);
    }
#pragma unroll 2
    for (int k = 1; k < 8; k++) {
        int idx = k * 32 + lane;
        uint4 h = hv[idx];
        duh(p0[idx], h, a0);
        duh(p1[idx], h, a1);
        duh(p2[idx], h, a2);
        duh(p3[idx], h, a3);
    }
    return make_float4(wreduce(accsum(a0)), wreduce(accsum(a1)),
                       wreduce(accsum(a2)), wreduce(accsum(a3)));
}

// 4 gate rows from explicit pointers (smem and/or global)
__device__ __forceinline__ float4 dot_pin(const __half* si, const __half* sf,
                                          const __half* sg,
                                          const __half* wo,
                                          const uint4* __restrict__ hv, int lane) {
    const uint4* pi = (const uint4*)si;
    const uint4* pf = (const uint4*)sf;
    const uint4* pg = (const uint4*)sg;
    const uint4* po = (const uint4*)wo;
    unsigned long long a0 = 0ull, a1 = 0ull, a2 = 0ull, a3 = 0ull;
#pragma unroll 2
    for (int k = 0; k < 8; k++) {
        int idx = k * 32 + lane;
        uint4 h = hv[idx];
        duh(pi[idx], h, a0);
        duh(pf[idx], h, a1);
        duh(pg[idx], h, a2);
        duh(po[idx], h, a3);
    }
    return make_float4(wreduce(accsum(a0)), wreduce(accsum(a1)),
                       wreduce(accsum(a2)), wreduce(accsum(a3)));
}

// fp32 warp dot (proj kernel only)
__device__ __forceinline__ float warp_dot(const float4* __restrict__ w,
                                          const float4* __restrict__ sh,
                                          int lane) {
    float ax = 0.f, ay = 0.f, az = 0.f, aw = 0.f;
#pragma unroll
    for (int k = 0; k < 16; k++) {
        float4 wv = w[k * 32 + lane];
        float4 hv = sh[k * 32 + lane];
        ax += wv.x * hv.x; ay += wv.y * hv.y;
        az += wv.z * hv.z; aw += wv.w * hv.w;
    }
    return wreduce((ax + ay) + (az + aw));
}

// ---------------- kernel 0: fp32 -> fp16 weight conversion -------------------
__global__ void cvt_kernel(const float* __restrict__ A,
                           const float* __restrict__ B,
                           const float* __restrict__ C) {
    size_t n4 = WELEM / 4;
    size_t stride = (size_t)gridDim.x * blockDim.x;
    for (size_t i = (size_t)blockIdx.x * blockDim.x + threadIdx.x; i < n4; i += stride) {
        float4 a = ((const float4*)A)[i];
        float4 b = ((const float4*)B)[i];
        float4 c = ((const float4*)C)[i];
        ((__half2*)g_whh1)[2*i]   = __floats2half2_rn(a.x, a.y);
        ((__half2*)g_whh1)[2*i+1] = __floats2half2_rn(a.z, a.w);
        ((__half2*)g_wih2)[2*i]   = __floats2half2_rn(b.x, b.y);
        ((__half2*)g_wih2)[2*i+1] = __floats2half2_rn(b.z, b.w);
        ((__half2*)g_whh2)[2*i]   = __floats2half2_rn(c.x, c.y);
        ((__half2*)g_whh2)[2*i+1] = __floats2half2_rn(c.z, c.w);
    }
}

// ---------------- kernel 1: pre1[t][row] = b1 + W_ih1[row,:] @ y[t,:] --------
__global__ void pre1_kernel(const float* __restrict__ y,
                            const float* __restrict__ W_ih1,
                            const float* __restrict__ b_ih1,
                            const float* __restrict__ b_hh1) {
    __shared__ float sy[64 * Dd];
    int row = blockIdx.x * 128 + threadIdx.x;
    int t0 = blockIdx.y * 64;
    for (int i = threadIdx.x; i < 64 * Dd; i += 128)
        sy[i] = y[(size_t)t0 * Dd + i];
    __syncthreads();

    float w[Dd];
#pragma unroll
    for (int k = 0; k < Dd; k++) w[k] = W_ih1[(size_t)row * Dd + k];
    float b = b_ih1[row] + b_hh1[row];

    for (int tt = 0; tt < 64; tt++) {
        float acc = b;
#pragma unroll
        for (int k = 0; k < Dd; k++) acc += w[k] * sy[tt * Dd + k];
        __stcs(&g_pre1[(size_t)(t0 + tt) * G4H + row], __float2half_rn(acc));
    }
}

// ---------------- kernel 2: persistent fused LSTM (1 barrier / step) ---------
// R13 dot engine (chunk-8 HFMA2, unroll 2) + fp16 h double buffers in global
// (owners write fp16 once; staging is a raw uint4 copy, no conversions).
__global__ void __launch_bounds__(NTHR, 1)
lstm_kernel(const float* __restrict__ b_ih2,
            const float* __restrict__ b_hh2) {
    extern __shared__ __half swei[];   // [3*nj + 8][Hh]
    __shared__ __half sAh[Hh];      // h1[t] fp16
    __shared__ __half sBh[Hh];      // h2[t-1] fp16
    __shared__ float sg1[64];
    __shared__ float sg2[2][64];
    __shared__ float sbias[64];
    __shared__ float spre[64];
    __shared__ float sc1[16];
    __shared__ float sc2[16];

    const int tid  = threadIdx.x;
    const int lane = tid & 31;
    const int warp = tid >> 5;
    const int b    = blockIdx.x;

    const int base  = Hh / NBLK;          // 13
    const int extra = Hh % NBLK;          // 124
    const int nj = base + (b < extra ? 1 : 0);
    const int j0 = b * base + (b < extra ? b : extra);

    unsigned bgen = g_release;

    // pin W_hh1 i,f,g rows + W_hh2 units 0,1 into smem (coalesced, one-time)
    const int segs = Hh / 8;               // 256 uint4 per row
    const int prows = 3 * nj + 8;
    for (int i = tid; i < prows * segs; i += NTHR) {
        int row = i / segs;
        int seg = i - row * segs;
        const __half* src;
        if (row < 3 * nj) {
            int g = row / nj, j = row - g * nj;
            src = g_whh1 + ((size_t)g * Hh + j0 + j) * Hh;
        } else {
            int rr = row - 3 * nj;
            int j = rr >> 2, q = rr & 3;
            src = g_whh2 + ((size_t)q * Hh + j0 + j) * Hh;
        }
        ((uint4*)(swei + (size_t)row * Hh))[seg] = ((const uint4*)src)[seg];
    }

    for (int j = tid; j < nj; j += NTHR) g_h2h[0][j0 + j] = __float2half_rn(0.f);
    for (int r = tid; r < 4 * nj; r += NTHR) {
        int j = r >> 2, q = r & 3;
        sbias[r] = b_ih2[q * Hh + j0 + j] + b_hh2[q * Hh + j0 + j];
    }
    if (tid < 16) { sc1[tid] = 0.f; sc2[tid] = 0.f; }
    __syncthreads();

    // prologue: h1[0] = cell1(x0, 0, 0)
    if (tid < nj) {
        size_t pb = (size_t)j0 + tid;
        float gi = sigf (__half2float(__ldcs(&g_pre1[pb])));
        float gg = tanhf(__half2float(__ldcs(&g_pre1[pb + 2 * Hh])));
        float go = sigf (__half2float(__ldcs(&g_pre1[pb + 3 * Hh])));
        float c = gi * gg;
        sc1[tid] = c;
        g_h1h[0][j0 + tid] = __float2half_rn(go * tanhf(c));
    }

    const __half* pfbase = g_wih2 + (size_t)(j0 + warp) * Hh;
    uint4 pf0 = {0,0,0,0}, pf1 = {0,0,0,0}, pf2 = {0,0,0,0}, pf3 = {0,0,0,0};

    gbar_arrive(++bgen);
    if (warp < nj) {
        pf0 = ((const uint4*)pfbase)[lane];
        pf1 = ((const uint4*)(pfbase + WSTRIDE))[lane];
        pf2 = ((const uint4*)(pfbase + 2 * WSTRIDE))[lane];
        pf3 = ((const uint4*)(pfbase + 3 * WSTRIDE))[lane];
    }
    gbar_wait(bgen);

    for (int t = 0; t < Tt; t++) {
        const int p = t & 1;
        const bool last = (t == Tt - 1);

        if (!last && tid < 64) {
            int q = tid >> 4, jj = tid & 15;
            if (jj < nj)
                spre[jj * 4 + q] = __half2float(
                    __ldcs(&g_pre1[(size_t)(t + 1) * G4H + q * Hh + j0 + jj]));
        }
        // stage h1[t], h2[t-1]: raw uint4 copy (fp16 already, no conversion)
        if (tid < 256) {
            ((uint4*)sAh)[tid] = ((const uint4*)g_h1h[p])[tid];
        } else {
            ((uint4*)sBh)[tid - 256] = ((const uint4*)g_h2h[p])[tid - 256];
        }
        __syncthreads();

        const int ntask = last ? 2 * nj : 3 * nj;
        for (int task = warp; task < ntask; task += NWARP) {
            if (task < nj) {
                // W_ih2 round-0 (task == warp): k=0 from prefetch regs
                float4 r = dot4g_pf(g_wih2 + (size_t)(j0 + task) * Hh,
                                    (const uint4*)sAh, lane, pf0, pf1, pf2, pf3);
                if (lane == 0) {
                    float* dst = &sg2[0][task * 4];
                    dst[0] = r.x; dst[1] = r.y; dst[2] = r.z; dst[3] = r.w;
                }
            } else if (task < nj + 2) {
                // W_hh2 units 0,1: fully smem-pinned
                int j = task - nj;
                const __half* s0 = swei + (size_t)(3 * nj + j * 4) * Hh;
                float4 r = dot_pin(s0, s0 + Hh, s0 + 2 * Hh, s0 + 3 * Hh,
                                   (const uint4*)sBh, lane);
                if (lane == 0) {
                    float* dst = &sg2[1][j * 4];
                    dst[0] = r.x; dst[1] = r.y; dst[2] = r.z; dst[3] = r.w;
                }
            } else if (task < 2 * nj) {
                int j = task - nj;
                float4 r = dot4g(g_whh2 + (size_t)(j0 + j) * Hh,
                                 (const uint4*)sBh, lane);
                if (lane == 0) {
                    float* dst = &sg2[1][j * 4];
                    dst[0] = r.x; dst[1] = r.y; dst[2] = r.z; dst[3] = r.w;
                }
            } else {
                int j = task - 2 * nj;
                float4 r = dot_pin(swei + (size_t)j * Hh,
                                   swei + (size_t)(nj + j) * Hh,
                                   swei + (size_t)(2 * nj + j) * Hh,
                                   g_whh1 + ((size_t)3 * Hh + j0 + j) * Hh,
                                   (const uint4*)sAh, lane);
                if (lane == 0) {
                    sg1[j * 4 + 0] = r.x; sg1[j * 4 + 1] = r.y;
                    sg1[j * 4 + 2] = r.z; sg1[j * 4 + 3] = r.w;
                }
            }
        }
        __syncthreads();

        if (tid < nj) {
            float gi = sigf (sg2[0][tid*4+0] + sg2[1][tid*4+0] + sbias[tid*4+0]);
            float gf = sigf (sg2[0][tid*4+1] + sg2[1][tid*4+1] + sbias[tid*4+1]);
            float gg = tanhf(sg2[0][tid*4+2] + sg2[1][tid*4+2] + sbias[tid*4+2]);
            float go = sigf (sg2[0][tid*4+3] + sg2[1][tid*4+3] + sbias[tid*4+3]);
            float c = gf * sc2[tid] + gi * gg;
            sc2[tid] = c;
            float hn = go * tanhf(c);
            g_h2h[1 - p][j0 + tid] = __float2half_rn(hn);
            __stcs(&g_h2hist[t][j0 + tid], hn);
        } else if (tid >= 32 && tid < 32 + nj && !last) {
            int u = tid - 32;
            float gi = sigf (sg1[u*4+0] + spre[u*4+0]);
            float gf = sigf (sg1[u*4+1] + spre[u*4+1]);
            float gg = tanhf(sg1[u*4+2] + spre[u*4+2]);
            float go = sigf (sg1[u*4+3] + spre[u*4+3]);
            float c = gf * sc1[u] + gi * gg;
            sc1[u] = c;
            g_h1h[1 - p][j0 + u] = __float2half_rn(go * tanhf(c));
        }

        gbar_arrive(++bgen);
        if (warp < nj && !last) {
            pf0 = ((const uint4*)pfbase)[lane];
            pf1 = ((const uint4*)(pfbase + WSTRIDE))[lane];
            pf2 = ((const uint4*)(pfbase + 2 * WSTRIDE))[lane];
            pf3 = ((const uint4*)(pfbase + 3 * WSTRIDE))[lane];
        }
        gbar_wait(bgen);
    }
}

// ---------------- kernel 3: output projection --------------------------------
__global__ void proj_kernel(const float* __restrict__ W_lin,
                            const float* __restrict__ b_lin,
                            float* __restrict__ out,
                            int prelen) {
    __shared__ float sh[Hh];
    const int t = prelen + blockIdx.x;
    const int tid = threadIdx.x;
    const int lane = tid & 31;
    const int warp = tid >> 5;

    for (int i = tid; i < Hh / 4; i += 256)
        ((float4*)sh)[i] = ((const float4*)&g_h2hist[t][0])[i];
    __syncthreads();

    for (int d = warp; d < Dd; d += 8) {
        float s = warp_dot((const float4*)(W_lin + (size_t)d * Hh),
                           (const float4*)sh, lane);
        if (lane == 0) out[(size_t)blockIdx.x * Dd + d] = s + b_lin[d];
    }
}

extern "C" void kernel_launch(void* const* d_in, const int* in_sizes, int n_in,
                              void* d_out, int out_size) {
    const float* y     = (const float*)d_in[0];
    const float* W_ih1 = (const float*)d_in[1];
    const float* W_hh1 = (const float*)d_in[2];
    const float* b_ih1 = (const float*)d_in[3];
    const float* b_hh1 = (const float*)d_in[4];
    const float* W_ih2 = (const float*)d_in[5];
    const float* W_hh2 = (const float*)d_in[6];
    const float* b_ih2 = (const float*)d_in[7];
    const float* b_hh2 = (const float*)d_in[8];
    const float* W_lin = (const float*)d_in[9];
    const float* b_lin = (const float*)d_in[10];
    (void)in_sizes; (void)n_in;

    const int nt = out_size / Dd;
    const int prelen = Tt - nt;

    cudaFuncSetAttribute(lstm_kernel,
                         cudaFuncAttributeMaxDynamicSharedMemorySize,
                         (int)SWBYTES);

    cvt_kernel<<<2048, 256>>>(W_hh1, W_ih2, W_hh2);
    dim3 g1(G4H / 128, Tt / 64);
    pre1_kernel<<<g1, 128>>>(y, W_ih1, b_ih1, b_hh1);
    lstm_kernel<<<NBLK, NTHR, SWBYTES>>>(b_ih2, b_hh2);
    proj_kernel<<<nt, 256>>>(W_lin, b_lin, (float*)d_out, prelen);
}

// round 16
// speedup vs baseline: 1.0343x; 1.0343x over previous
#include <cuda_runtime.h>
#include <cuda_fp16.h>
#include <math.h>

#define Hh 2048
#define Tt 4096
#define Dd 66
#define G4H (4*Hh)
#define NBLK 148
#define NTHR 512
#define NWARP (NTHR/32)
#define NJMAX 14
#define WELEM ((size_t)G4H*(size_t)Hh)
#define WSTRIDE ((size_t)Hh*(size_t)Hh)
// pinned: 3*nj rows W_hh1 (i,f,g) + 8 rows W_hh2 (units 0,1 all gates)
#define SWBYTES ((3*NJMAX + 8)*Hh*sizeof(__half))   // 204800 B
#define PACKED_ONE 0x3F8000003F800000ull

// ---------------- persistent device state (static; no runtime allocs) -------
__device__ float  g_h1[2][Hh];                     // h1 double buffer, fp32
__device__ float  g_h2[2][Hh];                     // h2 double buffer, fp32
__device__ float  g_h2hist[Tt][Hh];                // 33.5 MB (fp32, for proj)
__device__ __half g_pre1[(size_t)Tt * G4H];        // 67 MB fp16 (streamed, .cs)
__device__ __half g_whh1[WELEM];                   // 33.5 MB fp16
__device__ __half g_wih2[WELEM];
__device__ __half g_whh2[WELEM];

// flag barrier state (monotonic across graph replays) — central-release
__device__ volatile unsigned g_arrive[NBLK];
__device__ volatile unsigned g_release;

__device__ __forceinline__ float sigf(float x) { return 1.0f / (1.0f + expf(-x)); }

// ---------------- split central-release grid barrier --------------------------
__device__ __forceinline__ void gbar_arrive(unsigned target) {
    __syncthreads();
    if (blockIdx.x != 0 && threadIdx.x == 0) {
        __threadfence();
        g_arrive[blockIdx.x] = target;
    }
}
__device__ __forceinline__ void gbar_wait(unsigned target) {
    if (blockIdx.x == 0) {
        if (threadIdx.x > 0 && threadIdx.x < NBLK) {
            while ((int)(g_arrive[threadIdx.x] - target) < 0) { }
        }
        __syncthreads();
        if (threadIdx.x == 0) { __threadfence(); g_release = target; }
    } else {
        if (threadIdx.x == 0) {
            while ((int)(g_release - target) < 0) { }
            __threadfence();
        }
    }
    __syncthreads();
}

// ---------------- helpers ----------------------------------------------------
__device__ __forceinline__ float wreduce(float s) {
#pragma unroll
    for (int o = 16; o; o >>= 1) s += __shfl_down_sync(0xffffffffu, s, o);
    return s;
}

__device__ __forceinline__ unsigned long long cvt_h2_f2(unsigned h2) {
    unsigned long long r;
    asm("{\n\t"
        ".reg .f16 h0, h1;\n\t"
        ".reg .f32 f0, f1;\n\t"
        "mov.b32 {h0, h1}, %1;\n\t"
        "cvt.f32.f16 f0, h0;\n\t"
        "cvt.f32.f16 f1, h1;\n\t"
        "mov.b64 %0, {f0, f1};\n\t"
        "}" : "=l"(r) : "r"(h2));
    return r;
}

__device__ __forceinline__ void fma2(unsigned long long& acc,
                                     unsigned long long a,
                                     unsigned long long b) {
    asm("fma.rn.f32x2 %0, %1, %2, %3;" : "=l"(acc) : "l"(a), "l"(b), "l"(acc));
}

__device__ __forceinline__ float accsum(unsigned long long a) {
    float lo, hi;
    asm("mov.b64 {%0, %1}, %2;" : "=f"(lo), "=f"(hi) : "l"(a));
    return lo + hi;
}

// fp16 chunk-16 inner product: 16 weights x 16 h (two uint4s each), chained
// fp16 accumulate (1 HMUL2 + 7 HFMA2), ONE fold into the fp32x2 accumulator.
// (A/B-validated: R14 vs R15 shows chunk-16 beats chunk-8 by ~0.5 ms.)
__device__ __forceinline__ void duh2(uint4 wA, uint4 wB, uint4 hA, uint4 hB,
                                     unsigned long long& accf) {
    __half2 a =         __hmul2(*(__half2*)&wA.x, *(__half2*)&hA.x);
    a = __hfma2(*(__half2*)&wA.y, *(__half2*)&hA.y, a);
    a = __hfma2(*(__half2*)&wA.z, *(__half2*)&hA.z, a);
    a = __hfma2(*(__half2*)&wA.w, *(__half2*)&hA.w, a);
    a = __hfma2(*(__half2*)&wB.x, *(__half2*)&hB.x, a);
    a = __hfma2(*(__half2*)&wB.y, *(__half2*)&hB.y, a);
    a = __hfma2(*(__half2*)&wB.z, *(__half2*)&hB.z, a);
    a = __hfma2(*(__half2*)&wB.w, *(__half2*)&hB.w, a);
    fma2(accf, cvt_h2_f2(*(unsigned*)&a), PACKED_ONE);
}

// 4 gate rows streaming; h fp16 in smem. Pair loop: 10 uint4 live per iter.
__device__ __forceinline__ float4 dot4g(const __half* __restrict__ w0,
                                        const uint4* __restrict__ hv, int lane) {
    const uint4* p0 = (const uint4*)w0;
    const uint4* p1 = (const uint4*)(w0 + WSTRIDE);
    const uint4* p2 = (const uint4*)(w0 + 2 * WSTRIDE);
    const uint4* p3 = (const uint4*)(w0 + 3 * WSTRIDE);
    unsigned long long a0 = 0ull, a1 = 0ull, a2 = 0ull, a3 = 0ull;
#pragma unroll 1
    for (int k = 0; k < 8; k += 2) {
        int i0 = k * 32 + lane, i1 = i0 + 32;
        uint4 hA = hv[i0], hB = hv[i1];
        duh2(p0[i0], p0[i1], hA, hB, a0);
        duh2(p1[i0], p1[i1], hA, hB, a1);
        duh2(p2[i0], p2[i1], hA, hB, a2);
        duh2(p3[i0], p3[i1], hA, hB, a3);
    }
    return make_float4(wreduce(accsum(a0)), wreduce(accsum(a1)),
                       wreduce(accsum(a2)), wreduce(accsum(a3)));
}

// streaming with k=0 prefetched across the barrier window (pairs with k=1 loads)
__device__ __forceinline__ float4 dot4g_pf(const __half* __restrict__ w0,
                                           const uint4* __restrict__ hv, int lane,
                                           uint4 f0, uint4 f1, uint4 f2, uint4 f3) {
    const uint4* p0 = (const uint4*)w0;
    const uint4* p1 = (const uint4*)(w0 + WSTRIDE);
    const uint4* p2 = (const uint4*)(w0 + 2 * WSTRIDE);
    const uint4* p3 = (const uint4*)(w0 + 3 * WSTRIDE);
    unsigned long long a0 = 0ull, a1 = 0ull, a2 = 0ull, a3 = 0ull;
    {
        int i1 = 32 + lane;
        uint4 hA = hv[lane], hB = hv[i1];
        duh2(f0, p0[i1], hA, hB, a0);
        duh2(f1, p1[i1], hA, hB, a1);
        duh2(f2, p2[i1], hA, hB, a2);
        duh2(f3, p3[i1], hA, hB, a3);
    }
#pragma unroll 1
    for (int k = 2; k < 8; k += 2) {
        int i0 = k * 32 + lane, i1 = i0 + 32;
        uint4 hA = hv[i0], hB = hv[i1];
        duh2(p0[i0], p0[i1], hA, hB, a0);
        duh2(p1[i0], p1[i1], hA, hB, a1);
        duh2(p2[i0], p2[i1], hA, hB, a2);
        duh2(p3[i0], p3[i1], hA, hB, a3);
    }
    return make_float4(wreduce(accsum(a0)), wreduce(accsum(a1)),
                       wreduce(accsum(a2)), wreduce(accsum(a3)));
}

// 4 gate rows from explicit pointers (smem and/or global)
__device__ __forceinline__ float4 dot_pin(const __half* si, const __half* sf,
                                          const __half* sg,
                                          const __half* wo,
                                          const uint4* __restrict__ hv, int lane) {
    const uint4* pi = (const uint4*)si;
    const uint4* pf = (const uint4*)sf;
    const uint4* pg = (const uint4*)sg;
    const uint4* po = (const uint4*)wo;
    unsigned long long a0 = 0ull, a1 = 0ull, a2 = 0ull, a3 = 0ull;
#pragma unroll 1
    for (int k = 0; k < 8; k += 2) {
        int i0 = k * 32 + lane, i1 = i0 + 32;
        uint4 hA = hv[i0], hB = hv[i1];
        duh2(pi[i0], pi[i1], hA, hB, a0);
        duh2(pf[i0], pf[i1], hA, hB, a1);
        duh2(pg[i0], pg[i1], hA, hB, a2);
        duh2(po[i0], po[i1], hA, hB, a3);
    }
    return make_float4(wreduce(accsum(a0)), wreduce(accsum(a1)),
                       wreduce(accsum(a2)), wreduce(accsum(a3)));
}

// fp32 warp dot (proj kernel only)
__device__ __forceinline__ float warp_dot(const float4* __restrict__ w,
                                          const float4* __restrict__ sh,
                                          int lane) {
    float ax = 0.f, ay = 0.f, az = 0.f, aw = 0.f;
#pragma unroll
    for (int k = 0; k < 16; k++) {
        float4 wv = w[k * 32 + lane];
        float4 hv = sh[k * 32 + lane];
        ax += wv.x * hv.x; ay += wv.y * hv.y;
        az += wv.z * hv.z; aw += wv.w * hv.w;
    }
    return wreduce((ax + ay) + (az + aw));
}

// ---------------- kernel 0: fp32 -> fp16 weight conversion -------------------
__global__ void cvt_kernel(const float* __restrict__ A,
                           const float* __restrict__ B,
                           const float* __restrict__ C) {
    size_t n4 = WELEM / 4;
    size_t stride = (size_t)gridDim.x * blockDim.x;
    for (size_t i = (size_t)blockIdx.x * blockDim.x + threadIdx.x; i < n4; i += stride) {
        float4 a = ((const float4*)A)[i];
        float4 b = ((const float4*)B)[i];
        float4 c = ((const float4*)C)[i];
        ((__half2*)g_whh1)[2*i]   = __floats2half2_rn(a.x, a.y);
        ((__half2*)g_whh1)[2*i+1] = __floats2half2_rn(a.z, a.w);
        ((__half2*)g_wih2)[2*i]   = __floats2half2_rn(b.x, b.y);
        ((__half2*)g_wih2)[2*i+1] = __floats2half2_rn(b.z, b.w);
        ((__half2*)g_whh2)[2*i]   = __floats2half2_rn(c.x, c.y);
        ((__half2*)g_whh2)[2*i+1] = __floats2half2_rn(c.z, c.w);
    }
}

// ---------------- kernel 1: pre1[t][row] = b1 + W_ih1[row,:] @ y[t,:] --------
__global__ void pre1_kernel(const float* __restrict__ y,
                            const float* __restrict__ W_ih1,
                            const float* __restrict__ b_ih1,
                            const float* __restrict__ b_hh1) {
    __shared__ float sy[64 * Dd];
    int row = blockIdx.x * 128 + threadIdx.x;
    int t0 = blockIdx.y * 64;
    for (int i = threadIdx.x; i < 64 * Dd; i += 128)
        sy[i] = y[(size_t)t0 * Dd + i];
    __syncthreads();

    float w[Dd];
#pragma unroll
    for (int k = 0; k < Dd; k++) w[k] = W_ih1[(size_t)row * Dd + k];
    float b = b_ih1[row] + b_hh1[row];

    for (int tt = 0; tt < 64; tt++) {
        float acc = b;
#pragma unroll
        for (int k = 0; k < Dd; k++) acc += w[k] * sy[tt * Dd + k];
        __stcs(&g_pre1[(size_t)(t0 + tt) * G4H + row], __float2half_rn(acc));
    }
}

// ---------------- kernel 2: persistent fused LSTM (1 barrier / step) ---------
// R13 structure (fp32 h buffers, conversion staging) + chunk-16 fp16 engine.
__global__ void __launch_bounds__(NTHR, 1)
lstm_kernel(const float* __restrict__ b_ih2,
            const float* __restrict__ b_hh2) {
    extern __shared__ __half swei[];   // [3*nj + 8][Hh]
    __shared__ __half sAh[Hh];      // h1[t] fp16
    __shared__ __half sBh[Hh];      // h2[t-1] fp16
    __shared__ float sg1[64];
    __shared__ float sg2[2][64];
    __shared__ float sbias[64];
    __shared__ float spre[64];
    __shared__ float sc1[16];
    __shared__ float sc2[16];

    const int tid  = threadIdx.x;
    const int lane = tid & 31;
    const int warp = tid >> 5;
    const int b    = blockIdx.x;

    const int base  = Hh / NBLK;          // 13
    const int extra = Hh % NBLK;          // 124
    const int nj = base + (b < extra ? 1 : 0);
    const int j0 = b * base + (b < extra ? b : extra);

    unsigned bgen = g_release;

    // pin W_hh1 i,f,g rows + W_hh2 units 0,1 into smem (coalesced, one-time)
    const int segs = Hh / 8;               // 256 uint4 per row
    const int prows = 3 * nj + 8;
    for (int i = tid; i < prows * segs; i += NTHR) {
        int row = i / segs;
        int seg = i - row * segs;
        const __half* src;
        if (row < 3 * nj) {
            int g = row / nj, j = row - g * nj;
            src = g_whh1 + ((size_t)g * Hh + j0 + j) * Hh;
        } else {
            int rr = row - 3 * nj;
            int j = rr >> 2, q = rr & 3;
            src = g_whh2 + ((size_t)q * Hh + j0 + j) * Hh;
        }
        ((uint4*)(swei + (size_t)row * Hh))[seg] = ((const uint4*)src)[seg];
    }

    for (int j = tid; j < nj; j += NTHR) g_h2[0][j0 + j] = 0.f;
    for (int r = tid; r < 4 * nj; r += NTHR) {
        int j = r >> 2, q = r & 3;
        sbias[r] = b_ih2[q * Hh + j0 + j] + b_hh2[q * Hh + j0 + j];
    }
    if (tid < 16) { sc1[tid] = 0.f; sc2[tid] = 0.f; }
    __syncthreads();

    // prologue: h1[0] = cell1(x0, 0, 0)
    if (tid < nj) {
        size_t pb = (size_t)j0 + tid;
        float gi = sigf (__half2float(__ldcs(&g_pre1[pb])));
        float gg = tanhf(__half2float(__ldcs(&g_pre1[pb + 2 * Hh])));
        float go = sigf (__half2float(__ldcs(&g_pre1[pb + 3 * Hh])));
        float c = gi * gg;
        sc1[tid] = c;
        g_h1[0][j0 + tid] = go * tanhf(c);
    }

    const __half* pfbase = g_wih2 + (size_t)(j0 + warp) * Hh;
    uint4 pf0 = {0,0,0,0}, pf1 = {0,0,0,0}, pf2 = {0,0,0,0}, pf3 = {0,0,0,0};

    gbar_arrive(++bgen);
    if (warp < nj) {
        pf0 = ((const uint4*)pfbase)[lane];
        pf1 = ((const uint4*)(pfbase + WSTRIDE))[lane];
        pf2 = ((const uint4*)(pfbase + 2 * WSTRIDE))[lane];
        pf3 = ((const uint4*)(pfbase + 3 * WSTRIDE))[lane];
    }
    gbar_wait(bgen);

    for (int t = 0; t < Tt; t++) {
        const int p = t & 1;
        const bool last = (t == Tt - 1);

        if (!last && tid < 64) {
            int q = tid >> 4, jj = tid & 15;
            if (jj < nj)
                spre[jj * 4 + q] = __half2float(
                    __ldcs(&g_pre1[(size_t)(t + 1) * G4H + q * Hh + j0 + jj]));
        }
        // stage h1[t], h2[t-1] as fp16 (fp32 source, convert at staging)
        for (int i = tid; i < Hh / 4; i += NTHR) {
            float4 v = ((const float4*)g_h1[p])[i];
            ((__half2*)sAh)[2*i]   = __floats2half2_rn(v.x, v.y);
            ((__half2*)sAh)[2*i+1] = __floats2half2_rn(v.z, v.w);
            float4 w = ((const float4*)g_h2[p])[i];
            ((__half2*)sBh)[2*i]   = __floats2half2_rn(w.x, w.y);
            ((__half2*)sBh)[2*i+1] = __floats2half2_rn(w.z, w.w);
        }
        __syncthreads();

        const int ntask = last ? 2 * nj : 3 * nj;
        for (int task = warp; task < ntask; task += NWARP) {
            if (task < nj) {
                // W_ih2 round-0 (task == warp): k=0 from prefetch regs
                float4 r = dot4g_pf(g_wih2 + (size_t)(j0 + task) * Hh,
                                    (const uint4*)sAh, lane, pf0, pf1, pf2, pf3);
                if (lane == 0) {
                    float* dst = &sg2[0][task * 4];
                    dst[0] = r.x; dst[1] = r.y; dst[2] = r.z; dst[3] = r.w;
                }
            } else if (task < nj + 2) {
                // W_hh2 units 0,1: fully smem-pinned
                int j = task - nj;
                const __half* s0 = swei + (size_t)(3 * nj + j * 4) * Hh;
                float4 r = dot_pin(s0, s0 + Hh, s0 + 2 * Hh, s0 + 3 * Hh,
                                   (const uint4*)sBh, lane);
                if (lane == 0) {
                    float* dst = &sg2[1][j * 4];
                    dst[0] = r.x; dst[1] = r.y; dst[2] = r.z; dst[3] = r.w;
                }
            } else if (task < 2 * nj) {
                int j = task - nj;
                float4 r = dot4g(g_whh2 + (size_t)(j0 + j) * Hh,
                                 (const uint4*)sBh, lane);
                if (lane == 0) {
                    float* dst = &sg2[1][j * 4];
                    dst[0] = r.x; dst[1] = r.y; dst[2] = r.z; dst[3] = r.w;
                }
            } else {
                int j = task - 2 * nj;
                float4 r = dot_pin(swei + (size_t)j * Hh,
                                   swei + (size_t)(nj + j) * Hh,
                                   swei + (size_t)(2 * nj + j) * Hh,
                                   g_whh1 + ((size_t)3 * Hh + j0 + j) * Hh,
                                   (const uint4*)sAh, lane);
                if (lane == 0) {
                    sg1[j * 4 + 0] = r.x; sg1[j * 4 + 1] = r.y;
                    sg1[j * 4 + 2] = r.z; sg1[j * 4 + 3] = r.w;
                }
            }
        }
        __syncthreads();

        if (tid < nj) {
            float gi = sigf (sg2[0][tid*4+0] + sg2[1][tid*4+0] + sbias[tid*4+0]);
            float gf = sigf (sg2[0][tid*4+1] + sg2[1][tid*4+1] + sbias[tid*4+1]);
            float gg = tanhf(sg2[0][tid*4+2] + sg2[1][tid*4+2] + sbias[tid*4+2]);
            float go = sigf (sg2[0][tid*4+3] + sg2[1][tid*4+3] + sbias[tid*4+3]);
            float c = gf * sc2[tid] + gi * gg;
            sc2[tid] = c;
            float hn = go * tanhf(c);
            g_h2[1 - p][j0 + tid] = hn;
            __stcs(&g_h2hist[t][j0 + tid], hn);
        } else if (tid >= 32 && tid < 32 + nj && !last) {
            int u = tid - 32;
            float gi = sigf (sg1[u*4+0] + spre[u*4+0]);
            float gf = sigf (sg1[u*4+1] + spre[u*4+1]);
            float gg = tanhf(sg1[u*4+2] + spre[u*4+2]);
            float go = sigf (sg1[u*4+3] + spre[u*4+3]);
            float c = gf * sc1[u] + gi * gg;
            sc1[u] = c;
            g_h1[1 - p][j0 + u] = go * tanhf(c);
        }

        gbar_arrive(++bgen);
        if (warp < nj && !last) {
            pf0 = ((const uint4*)pfbase)[lane];
            pf1 = ((const uint4*)(pfbase + WSTRIDE))[lane];
            pf2 = ((const uint4*)(pfbase + 2 * WSTRIDE))[lane];
            pf3 = ((const uint4*)(pfbase + 3 * WSTRIDE))[lane];
        }
        gbar_wait(bgen);
    }
}

// ---------------- kernel 3: output projection --------------------------------
__global__ void proj_kernel(const float* __restrict__ W_lin,
                            const float* __restrict__ b_lin,
                            float* __restrict__ out,
                            int prelen) {
    __shared__ float sh[Hh];
    const int t = prelen + blockIdx.x;
    const int tid = threadIdx.x;
    const int lane = tid & 31;
    const int warp = tid >> 5;

    for (int i = tid; i < Hh / 4; i += 256)
        ((float4*)sh)[i] = ((const float4*)&g_h2hist[t][0])[i];
    __syncthreads();

    for (int d = warp; d < Dd; d += 8) {
        float s = warp_dot((const float4*)(W_lin + (size_t)d * Hh),
                           (const float4*)sh, lane);
        if (lane == 0) out[(size_t)blockIdx.x * Dd + d] = s + b_lin[d];
    }
}

extern "C" void kernel_launch(void* const* d_in, const int* in_sizes, int n_in,
                              void* d_out, int out_size) {
    const float* y     = (const float*)d_in[0];
    const float* W_ih1 = (const float*)d_in[1];
    const float* W_hh1 = (const float*)d_in[2];
    const float* b_ih1 = (const float*)d_in[3];
    const float* b_hh1 = (const float*)d_in[4];
    const float* W_ih2 = (const float*)d_in[5];
    const float* W_hh2 = (const float*)d_in[6];
    const float* b_ih2 = (const float*)d_in[7];
    const float* b_hh2 = (const float*)d_in[8];
    const float* W_lin = (const float*)d_in[9];
    const float* b_lin = (const float*)d_in[10];
    (void)in_sizes; (void)n_in;

    const int nt = out_size / Dd;
    const int prelen = Tt - nt;

    cudaFuncSetAttribute(lstm_kernel,
                         cudaFuncAttributeMaxDynamicSharedMemorySize,
                         (int)SWBYTES);

    cvt_kernel<<<2048, 256>>>(W_hh1, W_ih2, W_hh2);
    dim3 g1(G4H / 128, Tt / 64);
    pre1_kernel<<<g1, 128>>>(y, W_ih1, b_ih1, b_hh1);
    lstm_kernel<<<NBLK, NTHR, SWBYTES>>>(b_ih2, b_hh2);
    proj_kernel<<<nt, 256>>>(W_lin, b_lin, (float*)d_out, prelen);
}